// round 8
// baseline (speedup 1.0000x reference)
#include <cuda_runtime.h>
#include <cuda_fp16.h>
#include <math.h>

#define NN 50000
#define EE 400000
#define IN_CH 16
#define HID 32
#define KDIM 512          // HID*IN_CH
#define SROW 8192         // KDIM*IN_CH
#define CH 3200           // dst-chunk size (S = 52 MB, L2-resident)
#define NCHUNK 16
#define JSLICE 8
#define JLEN 1024         // SROW / JSLICE

// ---------------- scratch (static device globals; no allocations) ----------------
__device__ __half  g_Sh[(size_t)CH * SROW];      // [CH][8192] fp16  ~52 MB
__device__ __half  g_w2t[32 * SROW];             // w2 transposed+permuted [o][j']
__device__ __half2 g_w1h[256 * 16];              // w1 packed: [t][i] = (w1[i,2t], w1[i,2t+1])
__device__ __half2 g_b1h[256];
__device__ float   g_P[(size_t)JSLICE * NN * 32];// split-j partials, global rows (51 MB)
__device__ float   g_Xsum[NN * 16];
__device__ float   g_x1[NN * 32];
__device__ float   g_xw[NN * 32];
__device__ float   g_x2[NN * 32];
__device__ float   g_dis[NN];
__device__ int     g_cnt[NN];
__device__ int     g_offs[NN + 1];
__device__ int     g_cursor[NN];
__device__ int     g_elist[EE];
__device__ int     g_src[EE];
__device__ int     g_dst[EE];
__device__ int     g_is64;

// ---------------- [0] detect dtype + zero counters ----------------
__global__ void k_dz(const void* __restrict__ ei) {
    int i = blockIdx.x * blockDim.x + threadIdx.x;
    if (i < NN) g_cnt[i] = 0;
    if (i == 0) {
        const long long* p = (const long long*)ei;
        int ok = 1;
        #pragma unroll
        for (int q = 0; q < 16; ++q) {
            long long v = p[q];
            if (v < 0 || v >= NN) ok = 0;
        }
        g_is64 = ok;
    }
}

// ---------------- [1] decode edges + histogram ----------------
__global__ void k_prep(const void* __restrict__ ei) {
    int e = blockIdx.x * blockDim.x + threadIdx.x;
    if (e >= EE) return;
    int s, d;
    if (g_is64) {
        s = (int)((const long long*)ei)[e];
        d = (int)((const long long*)ei)[EE + e];
    } else {
        s = ((const int*)ei)[e];
        d = ((const int*)ei)[EE + e];
    }
    s = s < 0 ? 0 : (s >= NN ? NN - 1 : s);
    d = d < 0 ? 0 : (d >= NN ? NN - 1 : d);
    g_src[e] = s;
    g_dst[e] = d;
    atomicAdd(&g_cnt[d], 1);
}

// ---------------- [2] one-pass block scan ----------------
#define SCAN_PER 49
__global__ void k_scan() {
    __shared__ int wsum[32];
    int t = threadIdx.x, lane = t & 31, w = t >> 5;
    int base = t * SCAN_PER;
    int sum = 0;
    #pragma unroll 7
    for (int i = 0; i < SCAN_PER; ++i) {
        int idx = base + i;
        if (idx < NN) sum += g_cnt[idx];
    }
    int inc = sum;
    #pragma unroll
    for (int off = 1; off < 32; off <<= 1) {
        int y = __shfl_up_sync(0xffffffffu, inc, off);
        if (lane >= off) inc += y;
    }
    if (lane == 31) wsum[w] = inc;
    __syncthreads();
    if (w == 0) {
        int s = wsum[lane];
        #pragma unroll
        for (int off = 1; off < 32; off <<= 1) {
            int y = __shfl_up_sync(0xffffffffu, s, off);
            if (lane >= off) s += y;
        }
        wsum[lane] = s;
    }
    __syncthreads();
    int run = inc - sum + (w > 0 ? wsum[w - 1] : 0);
    #pragma unroll 7
    for (int i = 0; i < SCAN_PER; ++i) {
        int idx = base + i;
        if (idx < NN) {
            int v = g_cnt[idx];
            g_offs[idx]   = run;
            g_cursor[idx] = run;
            run += v;
        }
    }
    if (t == 0) g_offs[NN] = EE;
}

// ---------------- [3] scatter edges into dst-CSR ----------------
__global__ void k_scatter() {
    int e = blockIdx.x * blockDim.x + threadIdx.x;
    if (e >= EE) return;
    int pos = atomicAdd(&g_cursor[g_dst[e]], 1);
    if (pos >= 0 && pos < EE) g_elist[pos] = e;
}

// ---------------- [4] pack weights: w2t (permuted) + w1h + b1h ----------------
// j' = t*32 + 2*i + c  maps element (k = 2t+c, i); matches K1's half2 S layout.
__global__ void k_wpack(const float* __restrict__ w2, const float* __restrict__ w1,
                        const float* __restrict__ b1) {
    int idx = blockIdx.x * blockDim.x + threadIdx.x;
    if (idx < 32 * SROW) {
        int o  = idx >> 13;
        int jp = idx & (SROW - 1);
        int tt = jp >> 5;
        int r  = jp & 31;
        int i  = r >> 1;
        int c  = r & 1;
        int k  = 2 * tt + c;
        g_w2t[idx] = __float2half(w2[(size_t)k * KDIM + i * 32 + o]);
    }
    if (idx < 256 * 16) {
        int t = idx >> 4, i = idx & 15;
        g_w1h[idx] = __floats2half2_rn(w1[i * KDIM + 2 * t], w1[i * KDIM + 2 * t + 1]);
    }
    if (idx < 256)
        g_b1h[idx] = __floats2half2_rn(b1[2 * idx], b1[2 * idx + 1]);
}

// ---------------- degree norms ----------------
__global__ void k_dis() {
    int i = blockIdx.x * blockDim.x + threadIdx.x;
    if (i < NN) g_dis[i] = rsqrtf((float)(g_cnt[i] + 1));
}

// ---------------- K1: per-dst S row, half2 datapath, persistent blocks ----------------
__global__ __launch_bounds__(256) void k1_build_S(
    const float* __restrict__ x, const float* __restrict__ ea,
    int d0, int dn)
{
    int t = threadIdx.x;
    __half2 w1h[16];
    #pragma unroll
    for (int q = 0; q < 4; ++q)
        *(uint4*)&w1h[4 * q] = ((const uint4*)(g_w1h + t * 16))[q];
    __half2 b1h = g_b1h[t];
    const __half2 hz = __float2half2_rn(0.f);

    __shared__ __align__(16) __half2 eas[16][16];
    __shared__ __align__(16) __half2 xss[16][16];

    int lc = t >> 4;
    int li = t & 15;

    for (int dl = blockIdx.x; dl < dn; dl += gridDim.x) {
        int d = d0 + dl;
        __half2 S[16];
        #pragma unroll
        for (int i = 0; i < 16; ++i) S[i] = hz;
        float xsum = 0.f;

        int beg = g_offs[d], end = g_offs[d + 1];
        for (int base = beg; base < end; base += 16) {
            int nc = end - base; if (nc > 16) nc = 16;
            __syncthreads();
            if (lc < nc) {
                int e = g_elist[base + lc];
                int s = g_src[e];
                eas[lc][li] = __float2half2_rn(ea[(size_t)e * 16 + li]);
                xss[lc][li] = __float2half2_rn(x[(size_t)s * 16 + li]);
            }
            __syncthreads();
            for (int c = 0; c < nc; ++c) {
                __half2 er[16], xr[16];
                #pragma unroll
                for (int q = 0; q < 4; ++q) {
                    *(uint4*)&er[4 * q] = *(const uint4*)&eas[c][4 * q];
                    *(uint4*)&xr[4 * q] = *(const uint4*)&xss[c][4 * q];
                }
                __half2 rh = b1h;
                #pragma unroll
                for (int i = 0; i < 16; ++i)
                    rh = __hfma2(er[i], w1h[i], rh);
                rh = __hmax2(rh, hz);
                #pragma unroll
                for (int i = 0; i < 16; ++i)
                    S[i] = __hfma2(rh, xr[i], S[i]);
                if (t < 16) xsum += __low2float(xss[c][t]);
            }
        }
        uint4* Sp = (uint4*)(g_Sh + (size_t)dl * SROW + t * 32);
        #pragma unroll
        for (int q = 0; q < 4; ++q) Sp[q] = ((const uint4*)S)[q];
        if (t < 16) g_Xsum[d * 16 + t] = xsum;
    }
}

// ---------------- K2: tensor-core GEMM over a j-slice (ldmatrix) ----------------
#define AS_STRIDE 72
__global__ __launch_bounds__(256) void k2_mma(int d0, int dn)
{
    __shared__ __align__(16) __half As[128 * AS_STRIDE];
    __shared__ __align__(16) __half Bs[32 * AS_STRIDE];

    int tid  = threadIdx.x;
    int warp = tid >> 5;
    int lane = tid & 31;
    int g    = lane >> 2;
    int t4   = lane & 3;
    int slice = blockIdx.x & (JSLICE - 1);
    int r0    = (blockIdx.x >> 3) * 128;
    int jbase = slice * JLEN;

    float c0[4], c1[4], c2[4], c3[4];
    #pragma unroll
    for (int nt = 0; nt < 4; ++nt) { c0[nt] = 0.f; c1[nt] = 0.f; c2[nt] = 0.f; c3[nt] = 0.f; }

    // precomputed ldmatrix lane addresses (byte offsets within tiles)
    int aRow = (lane & 15);
    int aColOff = (lane >> 4) << 3;             // 0 or 8
    int bRow = ((lane >> 4) << 3) + (lane & 7); // 0..15
    int bColOff = (lane & 8);                   // 0 or 8

    for (int it = 0; it < JLEN / 64; ++it) {
        int j0 = jbase + it * 64;
        __syncthreads();
        #pragma unroll
        for (int u = 0; u < 4; ++u) {
            int idx = tid + u * 256;
            int row = idx >> 3;
            int q   = idx & 7;
            int rl  = r0 + row; if (rl >= dn) rl = dn - 1;
            *(uint4*)&As[row * AS_STRIDE + q * 8] =
                ((const uint4*)(g_Sh + (size_t)rl * SROW + j0))[q];
        }
        {
            int row = tid >> 3;
            int q   = tid & 7;
            *(uint4*)&Bs[row * AS_STRIDE + q * 8] =
                ((const uint4*)(g_w2t + (size_t)row * SROW + j0))[q];
        }
        __syncthreads();

        #pragma unroll
        for (int kk = 0; kk < 64; kk += 16) {
            unsigned a0, a1, a2, a3;
            {
                unsigned sa = (unsigned)__cvta_generic_to_shared(
                    &As[(warp * 16 + aRow) * AS_STRIDE + kk + aColOff]);
                asm volatile("ldmatrix.sync.aligned.m8n8.x4.shared.b16 {%0,%1,%2,%3}, [%4];"
                             : "=r"(a0), "=r"(a1), "=r"(a2), "=r"(a3) : "r"(sa));
            }
            unsigned b[8];
            {
                unsigned sb = (unsigned)__cvta_generic_to_shared(
                    &Bs[bRow * AS_STRIDE + kk + bColOff]);
                asm volatile("ldmatrix.sync.aligned.m8n8.x4.shared.b16 {%0,%1,%2,%3}, [%4];"
                             : "=r"(b[0]), "=r"(b[1]), "=r"(b[2]), "=r"(b[3]) : "r"(sb));
                unsigned sb2 = (unsigned)__cvta_generic_to_shared(
                    &Bs[(bRow + 16) * AS_STRIDE + kk + bColOff]);
                asm volatile("ldmatrix.sync.aligned.m8n8.x4.shared.b16 {%0,%1,%2,%3}, [%4];"
                             : "=r"(b[4]), "=r"(b[5]), "=r"(b[6]), "=r"(b[7]) : "r"(sb2));
            }
            #pragma unroll
            for (int nt = 0; nt < 4; ++nt) {
                asm volatile(
                    "mma.sync.aligned.m16n8k16.row.col.f32.f16.f16.f32 "
                    "{%0,%1,%2,%3}, {%4,%5,%6,%7}, {%8,%9}, {%0,%1,%2,%3};"
                    : "+f"(c0[nt]), "+f"(c1[nt]), "+f"(c2[nt]), "+f"(c3[nt])
                    : "r"(a0), "r"(a1), "r"(a2), "r"(a3), "r"(b[2 * nt]), "r"(b[2 * nt + 1]));
            }
        }
    }

    #pragma unroll
    for (int nt = 0; nt < 4; ++nt) {
        int row = r0 + warp * 16 + g;
        int col = nt * 8 + 2 * t4;
        if (row < dn)
            *(float2*)&g_P[((size_t)slice * NN + d0 + row) * 32 + col] = make_float2(c0[nt], c1[nt]);
        if (row + 8 < dn)
            *(float2*)&g_P[((size_t)slice * NN + d0 + row + 8) * 32 + col] = make_float2(c2[nt], c3[nt]);
    }
}

// ---------------- K2 reduce + NNConv epilogue -> x1 (one launch, all rows) ----------------
__global__ void k2_reduce(
    const float* __restrict__ b2, const float* __restrict__ x,
    const float* __restrict__ root, const float* __restrict__ nn_bias)
{
    int gid = blockIdx.x * blockDim.x + threadIdx.x;
    if (gid >= NN * 32) return;
    int d = gid >> 5, o = gid & 31;
    float v = nn_bias[o];
    #pragma unroll
    for (int s = 0; s < JSLICE; ++s)
        v += g_P[((size_t)s * NN + d) * 32 + o];
    #pragma unroll
    for (int i = 0; i < 16; ++i)
        v = fmaf(g_Xsum[d * 16 + i], b2[i * 32 + o], v);
    #pragma unroll
    for (int c = 0; c < 16; ++c)
        v = fmaf(x[(size_t)d * 16 + c], root[c * 32 + o], v);
    g_x1[d * 32 + o] = fmaxf(v, 0.f);
}

// ---------------- K3: xw = x1 @ gcn_w ----------------
__global__ void k3_xw(const float* __restrict__ gcn_w) {
    int gid = blockIdx.x * blockDim.x + threadIdx.x;
    if (gid >= NN * 32) return;
    int d = gid >> 5, o = gid & 31;
    float acc = 0.f;
    #pragma unroll
    for (int c = 0; c < 32; ++c)
        acc = fmaf(g_x1[d * 32 + c], gcn_w[c * 32 + o], acc);
    g_xw[gid] = acc;
}

// ---------------- K4: GCN aggregate via CSR (warp per dst) ----------------
__global__ void k4_gcn(const float* __restrict__ gcn_b) {
    int wid = (blockIdx.x * blockDim.x + threadIdx.x) >> 5;
    int lane = threadIdx.x & 31;
    int nwarps = (gridDim.x * blockDim.x) >> 5;
    for (int d = wid; d < NN; d += nwarps) {
        float dd = g_dis[d];
        float acc = 0.f;
        int beg = g_offs[d], end = g_offs[d + 1];
        for (int j = beg; j < end; ++j) {
            int e = g_elist[j];
            int s = g_src[e];
            acc = fmaf(g_dis[s], g_xw[s * 32 + lane], acc);
        }
        g_x2[d * 32 + lane] = gcn_b[lane] + dd * (dd * g_xw[d * 32 + lane] + acc);
    }
}

// ---------------- K5: edge scorer ----------------
__global__ void k5_score(const float* __restrict__ lin_w, const float* __restrict__ lin_b,
                         float* __restrict__ out) {
    int e = blockIdx.x * blockDim.x + threadIdx.x;
    if (e >= EE) return;
    int s = g_src[e], d = g_dst[e];
    const float4* a = (const float4*)(g_x2 + (size_t)s * 32);
    const float4* b = (const float4*)(g_x2 + (size_t)d * 32);
    const float4* w = (const float4*)lin_w;
    float acc = lin_b[0];
    #pragma unroll
    for (int q = 0; q < 8; ++q) {
        float4 av = a[q], wv = w[q];
        acc += av.x * wv.x + av.y * wv.y + av.z * wv.z + av.w * wv.w;
    }
    #pragma unroll
    for (int q = 0; q < 8; ++q) {
        float4 bv = b[q], wv = w[8 + q];
        acc += bv.x * wv.x + bv.y * wv.y + bv.z * wv.z + bv.w * wv.w;
    }
    out[e] = 1.f / (1.f + expf(-acc));
}

// ---------------- launch ----------------
extern "C" void kernel_launch(void* const* d_in, const int* in_sizes, int n_in,
                              void* d_out, int out_size) {
    const float* x       = (const float*)d_in[0];
    const void*  ei      = d_in[1];
    const float* ea      = (const float*)d_in[2];
    const float* w1      = (const float*)d_in[3];
    const float* b1      = (const float*)d_in[4];
    const float* w2      = (const float*)d_in[5];
    const float* b2      = (const float*)d_in[6];
    const float* root    = (const float*)d_in[7];
    const float* nn_bias = (const float*)d_in[8];
    const float* gcn_w   = (const float*)d_in[9];
    const float* gcn_b   = (const float*)d_in[10];
    const float* lin_w   = (const float*)d_in[11];
    const float* lin_b   = (const float*)d_in[12];
    float*       out     = (float*)d_out;

    k_dz<<<(NN + 255) / 256, 256>>>(ei);
    k_prep<<<(EE + 255) / 256, 256>>>(ei);
    k_scan<<<1, 1024>>>();
    k_scatter<<<(EE + 255) / 256, 256>>>();
    k_wpack<<<(32 * SROW + 255) / 256, 256>>>(w2, w1, b1);
    k_dis<<<(NN + 255) / 256, 256>>>();

    for (int c = 0; c < NCHUNK; ++c) {
        int d0 = c * CH;
        int dn = NN - d0; if (dn > CH) dn = CH;
        if (dn <= 0) break;
        int grid1 = dn < 592 ? dn : 592;
        k1_build_S<<<grid1, 256>>>(x, ea, d0, dn);
        int rtiles = (dn + 127) / 128;
        k2_mma<<<rtiles * JSLICE, 256>>>(d0, dn);
    }

    k2_reduce<<<(NN * 32 + 255) / 256, 256>>>(b2, x, root, nn_bias);
    k3_xw<<<(NN * 32 + 255) / 256, 256>>>(gcn_w);
    k4_gcn<<<512, 256>>>(gcn_b);
    k5_score<<<(EE + 255) / 256, 256>>>(lin_w, lin_b, out);
}

// round 9
// speedup vs baseline: 1.0721x; 1.0721x over previous
#include <cuda_runtime.h>
#include <cuda_fp16.h>
#include <math.h>

#define NN 50000
#define EE 400000
#define IN_CH 16
#define HID 32
#define KDIM 512          // HID*IN_CH
#define SROW 8192         // KDIM*IN_CH
#define CH 3200           // dst-chunk size (S = 52 MB, L2-resident)
#define NCHUNK 16
#define JSLICE 8
#define JLEN 1024         // SROW / JSLICE
#define K2ROWS 64         // rows per K2 tile

// ---------------- scratch (static device globals; no allocations) ----------------
__device__ __half  g_Sh[(size_t)CH * SROW];      // [CH][8192] fp16  ~52 MB
__device__ __half  g_w2t[32 * SROW];             // w2 transposed+permuted [o][j']
__device__ __half2 g_w1h[256 * 16];              // w1 packed: [t][i] = (w1[i,2t], w1[i,2t+1])
__device__ __half2 g_b1h[256];
__device__ float   g_P[JSLICE * CH * 32];        // split-j partials (3.3 MB, L2)
__device__ float   g_Xsum[NN * 16];
__device__ float   g_x1[NN * 32];
__device__ float   g_xw[NN * 32];
__device__ float   g_x2[NN * 32];
__device__ float   g_dis[NN];
__device__ int     g_cnt[NN];
__device__ int     g_offs[NN + 1];
__device__ int     g_cursor[NN];
__device__ int     g_elist[EE];
__device__ int     g_src[EE];
__device__ int     g_dst[EE];
__device__ int     g_is64;

// ---------------- [0] detect dtype + zero counters ----------------
__global__ void k_dz(const void* __restrict__ ei) {
    int i = blockIdx.x * blockDim.x + threadIdx.x;
    if (i < NN) g_cnt[i] = 0;
    if (i == 0) {
        const long long* p = (const long long*)ei;
        int ok = 1;
        #pragma unroll
        for (int q = 0; q < 16; ++q) {
            long long v = p[q];
            if (v < 0 || v >= NN) ok = 0;
        }
        g_is64 = ok;
    }
}

// ---------------- [1] decode edges + histogram ----------------
__global__ void k_prep(const void* __restrict__ ei) {
    int e = blockIdx.x * blockDim.x + threadIdx.x;
    if (e >= EE) return;
    int s, d;
    if (g_is64) {
        s = (int)((const long long*)ei)[e];
        d = (int)((const long long*)ei)[EE + e];
    } else {
        s = ((const int*)ei)[e];
        d = ((const int*)ei)[EE + e];
    }
    s = s < 0 ? 0 : (s >= NN ? NN - 1 : s);
    d = d < 0 ? 0 : (d >= NN ? NN - 1 : d);
    g_src[e] = s;
    g_dst[e] = d;
    atomicAdd(&g_cnt[d], 1);
}

// ---------------- [2] one-pass block scan ----------------
#define SCAN_PER 49
__global__ void k_scan() {
    __shared__ int wsum[32];
    int t = threadIdx.x, lane = t & 31, w = t >> 5;
    int base = t * SCAN_PER;
    int sum = 0;
    #pragma unroll 7
    for (int i = 0; i < SCAN_PER; ++i) {
        int idx = base + i;
        if (idx < NN) sum += g_cnt[idx];
    }
    int inc = sum;
    #pragma unroll
    for (int off = 1; off < 32; off <<= 1) {
        int y = __shfl_up_sync(0xffffffffu, inc, off);
        if (lane >= off) inc += y;
    }
    if (lane == 31) wsum[w] = inc;
    __syncthreads();
    if (w == 0) {
        int s = wsum[lane];
        #pragma unroll
        for (int off = 1; off < 32; off <<= 1) {
            int y = __shfl_up_sync(0xffffffffu, s, off);
            if (lane >= off) s += y;
        }
        wsum[lane] = s;
    }
    __syncthreads();
    int run = inc - sum + (w > 0 ? wsum[w - 1] : 0);
    #pragma unroll 7
    for (int i = 0; i < SCAN_PER; ++i) {
        int idx = base + i;
        if (idx < NN) {
            int v = g_cnt[idx];
            g_offs[idx]   = run;
            g_cursor[idx] = run;
            run += v;
        }
    }
    if (t == 0) g_offs[NN] = EE;
}

// ---------------- [3] scatter edges into dst-CSR ----------------
__global__ void k_scatter() {
    int e = blockIdx.x * blockDim.x + threadIdx.x;
    if (e >= EE) return;
    int pos = atomicAdd(&g_cursor[g_dst[e]], 1);
    if (pos >= 0 && pos < EE) g_elist[pos] = e;
}

// ---------------- [4] pack weights: w2t (permuted) + w1h + b1h ----------------
// j' = t*32 + 2*i + c  maps element (k = 2t+c, i); matches K1's half2 S layout.
__global__ void k_wpack(const float* __restrict__ w2, const float* __restrict__ w1,
                        const float* __restrict__ b1) {
    int idx = blockIdx.x * blockDim.x + threadIdx.x;
    if (idx < 32 * SROW) {
        int o  = idx >> 13;
        int jp = idx & (SROW - 1);
        int tt = jp >> 5;
        int r  = jp & 31;
        int i  = r >> 1;
        int c  = r & 1;
        int k  = 2 * tt + c;
        g_w2t[idx] = __float2half(w2[(size_t)k * KDIM + i * 32 + o]);
    }
    if (idx < 256 * 16) {
        int t = idx >> 4, i = idx & 15;
        g_w1h[idx] = __floats2half2_rn(w1[i * KDIM + 2 * t], w1[i * KDIM + 2 * t + 1]);
    }
    if (idx < 256)
        g_b1h[idx] = __floats2half2_rn(b1[2 * idx], b1[2 * idx + 1]);
}

// ---------------- degree norms ----------------
__global__ void k_dis() {
    int i = blockIdx.x * blockDim.x + threadIdx.x;
    if (i < NN) g_dis[i] = rsqrtf((float)(g_cnt[i] + 1));
}

// ---------------- K1: per-dst S row, half2 datapath ----------------
// Thread t owns k = {2t, 2t+1} packed as half2.
__global__ __launch_bounds__(256) void k1_build_S(
    const float* __restrict__ x, const float* __restrict__ ea,
    int d0, int dn)
{
    int t = threadIdx.x;
    __half2 w1h[16];
    #pragma unroll
    for (int q = 0; q < 4; ++q)
        *(uint4*)&w1h[4 * q] = ((const uint4*)(g_w1h + t * 16))[q];
    __half2 b1h = g_b1h[t];
    const __half2 hz = __float2half2_rn(0.f);

    __shared__ __align__(16) __half2 eas[16][16];
    __shared__ __align__(16) __half2 xss[16][16];

    int lc = t >> 4;
    int li = t & 15;

    for (int dl = blockIdx.x; dl < dn; dl += gridDim.x) {
        int d = d0 + dl;
        __half2 S[16];
        #pragma unroll
        for (int i = 0; i < 16; ++i) S[i] = hz;
        float xsum = 0.f;

        int beg = g_offs[d], end = g_offs[d + 1];
        for (int base = beg; base < end; base += 16) {
            int nc = end - base; if (nc > 16) nc = 16;
            __syncthreads();
            if (lc < nc) {
                int e = g_elist[base + lc];
                int s = g_src[e];
                eas[lc][li] = __float2half2_rn(ea[(size_t)e * 16 + li]);
                xss[lc][li] = __float2half2_rn(x[(size_t)s * 16 + li]);
            }
            __syncthreads();
            for (int c = 0; c < nc; ++c) {
                __half2 er[16], xr[16];
                #pragma unroll
                for (int q = 0; q < 4; ++q) {
                    *(uint4*)&er[4 * q] = *(const uint4*)&eas[c][4 * q];
                    *(uint4*)&xr[4 * q] = *(const uint4*)&xss[c][4 * q];
                }
                __half2 rh = b1h;
                #pragma unroll
                for (int i = 0; i < 16; ++i)
                    rh = __hfma2(er[i], w1h[i], rh);
                rh = __hmax2(rh, hz);
                #pragma unroll
                for (int i = 0; i < 16; ++i)
                    S[i] = __hfma2(rh, xr[i], S[i]);
                if (t < 16) xsum += __low2float(xss[c][t]);
            }
        }
        uint4* Sp = (uint4*)(g_Sh + (size_t)dl * SROW + t * 32);
        #pragma unroll
        for (int q = 0; q < 4; ++q) Sp[q] = ((const uint4*)S)[q];
        if (t < 16) g_Xsum[d * 16 + t] = xsum;
    }
}

// ---------------- K2: tensor-core GEMM over a j-slice ----------------
// tile = 64 rows x 32 o x JLEN j; 128 threads = 4 warps x 16 rows.
#define AS_STRIDE 72
__global__ __launch_bounds__(128) void k2_mma(int dn)
{
    __shared__ __align__(16) __half As[K2ROWS * AS_STRIDE];   // 9216 B
    __shared__ __align__(16) __half Bs[32 * AS_STRIDE];       // 4608 B

    int tid  = threadIdx.x;
    int warp = tid >> 5;
    int lane = tid & 31;
    int g    = lane >> 2;
    int t4   = lane & 3;
    int slice = blockIdx.x & (JSLICE - 1);
    int r0    = (blockIdx.x >> 3) * K2ROWS;
    int jbase = slice * JLEN;

    float c0[4], c1[4], c2[4], c3[4];
    #pragma unroll
    for (int nt = 0; nt < 4; ++nt) { c0[nt] = 0.f; c1[nt] = 0.f; c2[nt] = 0.f; c3[nt] = 0.f; }

    for (int it = 0; it < JLEN / 64; ++it) {
        int j0 = jbase + it * 64;
        __syncthreads();
        // A tile: 64 rows x 8 uint4 = 512 uint4; 128 thr x 4
        #pragma unroll
        for (int u = 0; u < 4; ++u) {
            int idx = tid + u * 128;
            int row = idx >> 3;
            int q   = idx & 7;
            int rl  = r0 + row; if (rl >= dn) rl = dn - 1;
            *(uint4*)&As[row * AS_STRIDE + q * 8] =
                ((const uint4*)(g_Sh + (size_t)rl * SROW + j0))[q];
        }
        // B tile: 32 rows x 8 uint4 = 256 uint4; 128 thr x 2
        #pragma unroll
        for (int u = 0; u < 2; ++u) {
            int idx = tid + u * 128;
            int row = idx >> 3;
            int q   = idx & 7;
            *(uint4*)&Bs[row * AS_STRIDE + q * 8] =
                ((const uint4*)(g_w2t + (size_t)row * SROW + j0))[q];
        }
        __syncthreads();

        #pragma unroll
        for (int kk = 0; kk < 64; kk += 16) {
            unsigned a0 = *(const unsigned*)&As[(warp * 16 + g    ) * AS_STRIDE + kk     + 2 * t4];
            unsigned a1 = *(const unsigned*)&As[(warp * 16 + g + 8) * AS_STRIDE + kk     + 2 * t4];
            unsigned a2 = *(const unsigned*)&As[(warp * 16 + g    ) * AS_STRIDE + kk + 8 + 2 * t4];
            unsigned a3 = *(const unsigned*)&As[(warp * 16 + g + 8) * AS_STRIDE + kk + 8 + 2 * t4];
            #pragma unroll
            for (int nt = 0; nt < 4; ++nt) {
                unsigned b0 = *(const unsigned*)&Bs[(nt * 8 + g) * AS_STRIDE + kk     + 2 * t4];
                unsigned b1 = *(const unsigned*)&Bs[(nt * 8 + g) * AS_STRIDE + kk + 8 + 2 * t4];
                asm volatile(
                    "mma.sync.aligned.m16n8k16.row.col.f32.f16.f16.f32 "
                    "{%0,%1,%2,%3}, {%4,%5,%6,%7}, {%8,%9}, {%0,%1,%2,%3};"
                    : "+f"(c0[nt]), "+f"(c1[nt]), "+f"(c2[nt]), "+f"(c3[nt])
                    : "r"(a0), "r"(a1), "r"(a2), "r"(a3), "r"(b0), "r"(b1));
            }
        }
    }

    #pragma unroll
    for (int nt = 0; nt < 4; ++nt) {
        int row = r0 + warp * 16 + g;
        int col = nt * 8 + 2 * t4;
        if (row < dn)
            *(float2*)&g_P[((size_t)slice * CH + row) * 32 + col] = make_float2(c0[nt], c1[nt]);
        if (row + 8 < dn)
            *(float2*)&g_P[((size_t)slice * CH + row + 8) * 32 + col] = make_float2(c2[nt], c3[nt]);
    }
}

// ---------------- K2 reduce + NNConv epilogue -> x1 (per chunk) ----------------
__global__ void k2_reduce(
    const float* __restrict__ b2, const float* __restrict__ x,
    const float* __restrict__ root, const float* __restrict__ nn_bias,
    int d0, int dn)
{
    int gid = blockIdx.x * blockDim.x + threadIdx.x;
    if (gid >= dn * 32) return;
    int rl = gid >> 5, o = gid & 31;
    int d = d0 + rl;
    float v = nn_bias[o];
    #pragma unroll
    for (int s = 0; s < JSLICE; ++s)
        v += g_P[((size_t)s * CH + rl) * 32 + o];
    #pragma unroll
    for (int i = 0; i < 16; ++i)
        v = fmaf(g_Xsum[d * 16 + i], b2[i * 32 + o], v);
    #pragma unroll
    for (int c = 0; c < 16; ++c)
        v = fmaf(x[(size_t)d * 16 + c], root[c * 32 + o], v);
    g_x1[d * 32 + o] = fmaxf(v, 0.f);
}

// ---------------- K3: xw = x1 @ gcn_w ----------------
__global__ void k3_xw(const float* __restrict__ gcn_w) {
    int gid = blockIdx.x * blockDim.x + threadIdx.x;
    if (gid >= NN * 32) return;
    int d = gid >> 5, o = gid & 31;
    float acc = 0.f;
    #pragma unroll
    for (int c = 0; c < 32; ++c)
        acc = fmaf(g_x1[d * 32 + c], gcn_w[c * 32 + o], acc);
    g_xw[gid] = acc;
}

// ---------------- K4: GCN aggregate via CSR (warp per dst) ----------------
__global__ void k4_gcn(const float* __restrict__ gcn_b) {
    int wid = (blockIdx.x * blockDim.x + threadIdx.x) >> 5;
    int lane = threadIdx.x & 31;
    int nwarps = (gridDim.x * blockDim.x) >> 5;
    for (int d = wid; d < NN; d += nwarps) {
        float dd = g_dis[d];
        float acc = 0.f;
        int beg = g_offs[d], end = g_offs[d + 1];
        for (int j = beg; j < end; ++j) {
            int e = g_elist[j];
            int s = g_src[e];
            acc = fmaf(g_dis[s], g_xw[s * 32 + lane], acc);
        }
        g_x2[d * 32 + lane] = gcn_b[lane] + dd * (dd * g_xw[d * 32 + lane] + acc);
    }
}

// ---------------- K5: edge scorer ----------------
__global__ void k5_score(const float* __restrict__ lin_w, const float* __restrict__ lin_b,
                         float* __restrict__ out) {
    int e = blockIdx.x * blockDim.x + threadIdx.x;
    if (e >= EE) return;
    int s = g_src[e], d = g_dst[e];
    const float4* a = (const float4*)(g_x2 + (size_t)s * 32);
    const float4* b = (const float4*)(g_x2 + (size_t)d * 32);
    const float4* w = (const float4*)lin_w;
    float acc = lin_b[0];
    #pragma unroll
    for (int q = 0; q < 8; ++q) {
        float4 av = a[q], wv = w[q];
        acc += av.x * wv.x + av.y * wv.y + av.z * wv.z + av.w * wv.w;
    }
    #pragma unroll
    for (int q = 0; q < 8; ++q) {
        float4 bv = b[q], wv = w[8 + q];
        acc += bv.x * wv.x + bv.y * wv.y + bv.z * wv.z + bv.w * wv.w;
    }
    out[e] = 1.f / (1.f + expf(-acc));
}

// ---------------- launch ----------------
extern "C" void kernel_launch(void* const* d_in, const int* in_sizes, int n_in,
                              void* d_out, int out_size) {
    const float* x       = (const float*)d_in[0];
    const void*  ei      = d_in[1];
    const float* ea      = (const float*)d_in[2];
    const float* w1      = (const float*)d_in[3];
    const float* b1      = (const float*)d_in[4];
    const float* w2      = (const float*)d_in[5];
    const float* b2      = (const float*)d_in[6];
    const float* root    = (const float*)d_in[7];
    const float* nn_bias = (const float*)d_in[8];
    const float* gcn_w   = (const float*)d_in[9];
    const float* gcn_b   = (const float*)d_in[10];
    const float* lin_w   = (const float*)d_in[11];
    const float* lin_b   = (const float*)d_in[12];
    float*       out     = (float*)d_out;

    k_dz<<<(NN + 255) / 256, 256>>>(ei);
    k_prep<<<(EE + 255) / 256, 256>>>(ei);
    k_scan<<<1, 1024>>>();
    k_scatter<<<(EE + 255) / 256, 256>>>();
    k_wpack<<<(32 * SROW + 255) / 256, 256>>>(w2, w1, b1);
    k_dis<<<(NN + 255) / 256, 256>>>();

    for (int c = 0; c < NCHUNK; ++c) {
        int d0 = c * CH;
        int dn = NN - d0; if (dn > CH) dn = CH;
        if (dn <= 0) break;
        int grid1 = dn < 2048 ? dn : 2048;
        k1_build_S<<<grid1, 256>>>(x, ea, d0, dn);
        int rtiles = (dn + K2ROWS - 1) / K2ROWS;
        k2_mma<<<rtiles * JSLICE, 128>>>(dn);
        k2_reduce<<<(dn * 32 + 255) / 256, 256>>>(b2, x, root, nn_bias, d0, dn);
    }

    k3_xw<<<(NN * 32 + 255) / 256, 256>>>(gcn_w);
    k4_gcn<<<512, 256>>>(gcn_b);
    k5_score<<<(EE + 255) / 256, 256>>>(lin_w, lin_b, out);
}

// round 10
// speedup vs baseline: 1.1320x; 1.0559x over previous
#include <cuda_runtime.h>
#include <cuda_fp16.h>
#include <math.h>

#define NN 50000
#define EE 400000
#define IN_CH 16
#define HID 32
#define KDIM 512          // HID*IN_CH
#define SROW 8192         // KDIM*IN_CH
#define CH 2560           // dst-chunk size
#define NCHUNK 20         // 19*2560=48640, last chunk 1360
#define JSLICE 8
#define JLEN 1024         // SROW / JSLICE
#define K1GRID 2048
#define AS_STRIDE 72

// ---------------- scratch (static device globals; no allocations) ----------------
__device__ __half  g_Sh[2][(size_t)CH * SROW];   // double-buffered S, 2 x 42 MB
__device__ float   g_P[2][JSLICE * CH * 32];     // double-buffered partials
__device__ __half  g_w2t[32 * SROW];
__device__ __half2 g_w1h[256 * 16];
__device__ __half2 g_b1h[256];
__device__ float   g_Xsum[NN * 16];
__device__ float   g_x1[NN * 32];
__device__ float   g_xw[NN * 32];
__device__ float   g_x2[NN * 32];
__device__ float   g_dis[NN];
__device__ int     g_cnt[NN];
__device__ int     g_offs[NN + 1];
__device__ int     g_cursor[NN];
__device__ int     g_elist[EE];
__device__ int     g_src[EE];
__device__ int     g_dst[EE];
__device__ int     g_is64;

// ---------------- [0] detect dtype + zero counters ----------------
__global__ void k_dz(const void* __restrict__ ei) {
    int i = blockIdx.x * blockDim.x + threadIdx.x;
    if (i < NN) g_cnt[i] = 0;
    if (i == 0) {
        const long long* p = (const long long*)ei;
        int ok = 1;
        #pragma unroll
        for (int q = 0; q < 16; ++q) {
            long long v = p[q];
            if (v < 0 || v >= NN) ok = 0;
        }
        g_is64 = ok;
    }
}

// ---------------- [1] decode edges + histogram ----------------
__global__ void k_prep(const void* __restrict__ ei) {
    int e = blockIdx.x * blockDim.x + threadIdx.x;
    if (e >= EE) return;
    int s, d;
    if (g_is64) {
        s = (int)((const long long*)ei)[e];
        d = (int)((const long long*)ei)[EE + e];
    } else {
        s = ((const int*)ei)[e];
        d = ((const int*)ei)[EE + e];
    }
    s = s < 0 ? 0 : (s >= NN ? NN - 1 : s);
    d = d < 0 ? 0 : (d >= NN ? NN - 1 : d);
    g_src[e] = s;
    g_dst[e] = d;
    atomicAdd(&g_cnt[d], 1);
}

// ---------------- [2] one-pass block scan (+ degree norms) ----------------
#define SCAN_PER 49
__global__ void k_scan() {
    __shared__ int wsum[32];
    int t = threadIdx.x, lane = t & 31, w = t >> 5;
    int base = t * SCAN_PER;
    int sum = 0;
    #pragma unroll 7
    for (int i = 0; i < SCAN_PER; ++i) {
        int idx = base + i;
        if (idx < NN) sum += g_cnt[idx];
    }
    int inc = sum;
    #pragma unroll
    for (int off = 1; off < 32; off <<= 1) {
        int y = __shfl_up_sync(0xffffffffu, inc, off);
        if (lane >= off) inc += y;
    }
    if (lane == 31) wsum[w] = inc;
    __syncthreads();
    if (w == 0) {
        int s = wsum[lane];
        #pragma unroll
        for (int off = 1; off < 32; off <<= 1) {
            int y = __shfl_up_sync(0xffffffffu, s, off);
            if (lane >= off) s += y;
        }
        wsum[lane] = s;
    }
    __syncthreads();
    int run = inc - sum + (w > 0 ? wsum[w - 1] : 0);
    #pragma unroll 7
    for (int i = 0; i < SCAN_PER; ++i) {
        int idx = base + i;
        if (idx < NN) {
            int v = g_cnt[idx];
            g_offs[idx]   = run;
            g_cursor[idx] = run;
            g_dis[idx]    = rsqrtf((float)(v + 1));
            run += v;
        }
    }
    if (t == 0) g_offs[NN] = EE;
}

// ---------------- [3] scatter edges into dst-CSR ----------------
__global__ void k_scatter() {
    int e = blockIdx.x * blockDim.x + threadIdx.x;
    if (e >= EE) return;
    int pos = atomicAdd(&g_cursor[g_dst[e]], 1);
    if (pos >= 0 && pos < EE) g_elist[pos] = e;
}

// ---------------- [4] pack weights ----------------
__global__ void k_wpack(const float* __restrict__ w2, const float* __restrict__ w1,
                        const float* __restrict__ b1) {
    int idx = blockIdx.x * blockDim.x + threadIdx.x;
    if (idx < 32 * SROW) {
        int o  = idx >> 13;
        int jp = idx & (SROW - 1);
        int tt = jp >> 5;
        int r  = jp & 31;
        int i  = r >> 1;
        int c  = r & 1;
        int k  = 2 * tt + c;
        g_w2t[idx] = __float2half(w2[(size_t)k * KDIM + i * 32 + o]);
    }
    if (idx < 256 * 16) {
        int t = idx >> 4, i = idx & 15;
        g_w1h[idx] = __floats2half2_rn(w1[i * KDIM + 2 * t], w1[i * KDIM + 2 * t + 1]);
    }
    if (idx < 256)
        g_b1h[idx] = __floats2half2_rn(b1[2 * idx], b1[2 * idx + 1]);
}

// ================= combo roles =================

// --- role A: K1 build S rows for chunk cc into g_Sh[cc&1] ---
__device__ __forceinline__ void k1_role(
    unsigned char* sm, int bid, int ngrid,
    const float* __restrict__ x, const float* __restrict__ ea,
    int cc, int dn)
{
    int t = threadIdx.x;
    __half* Sbuf = g_Sh[cc & 1];
    int d0 = cc * CH;

    __half2 w1h[16];
    #pragma unroll
    for (int q = 0; q < 4; ++q)
        *(uint4*)&w1h[4 * q] = ((const uint4*)(g_w1h + t * 16))[q];
    __half2 b1h = g_b1h[t];
    const __half2 hz = __float2half2_rn(0.f);

    __half2 (*eas)[16] = (__half2(*)[16])sm;
    __half2 (*xss)[16] = (__half2(*)[16])(sm + 16 * 16 * sizeof(__half2));

    int lc = t >> 4;
    int li = t & 15;

    for (int dl = bid; dl < dn; dl += ngrid) {
        int d = d0 + dl;
        __half2 S[16];
        #pragma unroll
        for (int i = 0; i < 16; ++i) S[i] = hz;
        float xsum = 0.f;

        int beg = g_offs[d], end = g_offs[d + 1];
        for (int base = beg; base < end; base += 16) {
            int nc = end - base; if (nc > 16) nc = 16;
            __syncthreads();
            if (lc < nc) {
                int e = g_elist[base + lc];
                int s = g_src[e];
                eas[lc][li] = __float2half2_rn(ea[(size_t)e * 16 + li]);
                xss[lc][li] = __float2half2_rn(x[(size_t)s * 16 + li]);
            }
            __syncthreads();
            for (int c = 0; c < nc; ++c) {
                __half2 er[16], xr[16];
                #pragma unroll
                for (int q = 0; q < 4; ++q) {
                    *(uint4*)&er[4 * q] = *(const uint4*)&eas[c][4 * q];
                    *(uint4*)&xr[4 * q] = *(const uint4*)&xss[c][4 * q];
                }
                __half2 rh = b1h;
                #pragma unroll
                for (int i = 0; i < 16; ++i)
                    rh = __hfma2(er[i], w1h[i], rh);
                rh = __hmax2(rh, hz);
                #pragma unroll
                for (int i = 0; i < 16; ++i)
                    S[i] = __hfma2(rh, xr[i], S[i]);
                if (t < 16) xsum += __low2float(xss[c][t]);
            }
        }
        uint4* Sp = (uint4*)(Sbuf + (size_t)dl * SROW + t * 32);
        #pragma unroll
        for (int q = 0; q < 4; ++q) Sp[q] = ((const uint4*)S)[q];
        if (t < 16) g_Xsum[d * 16 + t] = xsum;
    }
}

// --- role B: K2 MMA over a j-slice for chunk cc (reads g_Sh[cc&1], writes g_P[cc&1]) ---
__device__ __forceinline__ void k2_role(unsigned char* sm, int bid, int cc, int dn)
{
    __half* As = (__half*)sm;                              // 128*72 halves
    __half* Bs = (__half*)(sm + 128 * AS_STRIDE * 2);      // 32*72 halves
    const __half* Sbuf = g_Sh[cc & 1];
    float* Pbuf = g_P[cc & 1];

    int tid  = threadIdx.x;
    int warp = tid >> 5;
    int lane = tid & 31;
    int g    = lane >> 2;
    int t4   = lane & 3;
    int slice = bid & (JSLICE - 1);
    int r0    = (bid >> 3) * 128;
    int jbase = slice * JLEN;

    float c0[4], c1[4], c2[4], c3[4];
    #pragma unroll
    for (int nt = 0; nt < 4; ++nt) { c0[nt] = 0.f; c1[nt] = 0.f; c2[nt] = 0.f; c3[nt] = 0.f; }

    for (int it = 0; it < JLEN / 64; ++it) {
        int j0 = jbase + it * 64;
        __syncthreads();
        #pragma unroll
        for (int u = 0; u < 4; ++u) {
            int idx = tid + u * 256;
            int row = idx >> 3;
            int q   = idx & 7;
            int rl  = r0 + row; if (rl >= dn) rl = dn - 1;
            *(uint4*)&As[row * AS_STRIDE + q * 8] =
                ((const uint4*)(Sbuf + (size_t)rl * SROW + j0))[q];
        }
        {
            int row = tid >> 3;
            int q   = tid & 7;
            *(uint4*)&Bs[row * AS_STRIDE + q * 8] =
                ((const uint4*)(g_w2t + (size_t)row * SROW + j0))[q];
        }
        __syncthreads();

        #pragma unroll
        for (int kk = 0; kk < 64; kk += 16) {
            unsigned a0 = *(const unsigned*)&As[(warp * 16 + g    ) * AS_STRIDE + kk     + 2 * t4];
            unsigned a1 = *(const unsigned*)&As[(warp * 16 + g + 8) * AS_STRIDE + kk     + 2 * t4];
            unsigned a2 = *(const unsigned*)&As[(warp * 16 + g    ) * AS_STRIDE + kk + 8 + 2 * t4];
            unsigned a3 = *(const unsigned*)&As[(warp * 16 + g + 8) * AS_STRIDE + kk + 8 + 2 * t4];
            #pragma unroll
            for (int nt = 0; nt < 4; ++nt) {
                unsigned b0 = *(const unsigned*)&Bs[(nt * 8 + g) * AS_STRIDE + kk     + 2 * t4];
                unsigned b1 = *(const unsigned*)&Bs[(nt * 8 + g) * AS_STRIDE + kk + 8 + 2 * t4];
                asm volatile(
                    "mma.sync.aligned.m16n8k16.row.col.f32.f16.f16.f32 "
                    "{%0,%1,%2,%3}, {%4,%5,%6,%7}, {%8,%9}, {%0,%1,%2,%3};"
                    : "+f"(c0[nt]), "+f"(c1[nt]), "+f"(c2[nt]), "+f"(c3[nt])
                    : "r"(a0), "r"(a1), "r"(a2), "r"(a3), "r"(b0), "r"(b1));
            }
        }
    }

    #pragma unroll
    for (int nt = 0; nt < 4; ++nt) {
        int row = r0 + warp * 16 + g;
        int col = nt * 8 + 2 * t4;
        if (row < dn)
            *(float2*)&Pbuf[((size_t)slice * CH + row) * 32 + col] = make_float2(c0[nt], c1[nt]);
        if (row + 8 < dn)
            *(float2*)&Pbuf[((size_t)slice * CH + row + 8) * 32 + col] = make_float2(c2[nt], c3[nt]);
    }
}

// --- role C: reduce partials + NNConv epilogue for chunk cc ---
__device__ __forceinline__ void red_role(
    int bid, int cc, int dn,
    const float* __restrict__ b2, const float* __restrict__ x,
    const float* __restrict__ root, const float* __restrict__ nn_bias)
{
    int gid = bid * 256 + threadIdx.x;
    if (gid >= dn * 32) return;
    const float* Pbuf = g_P[cc & 1];
    int rl = gid >> 5, o = gid & 31;
    int d = cc * CH + rl;
    float v = nn_bias[o];
    #pragma unroll
    for (int s = 0; s < JSLICE; ++s)
        v += Pbuf[((size_t)s * CH + rl) * 32 + o];
    #pragma unroll
    for (int i = 0; i < 16; ++i)
        v = fmaf(g_Xsum[d * 16 + i], b2[i * 32 + o], v);
    #pragma unroll
    for (int c = 0; c < 16; ++c)
        v = fmaf(x[(size_t)d * 16 + c], root[c * 32 + o], v);
    g_x1[d * 32 + o] = fmaxf(v, 0.f);
}

// --- combo: block ranges -> roles (no intra-launch dependencies) ---
__global__ __launch_bounds__(256) void k_combo(
    const float* __restrict__ x, const float* __restrict__ ea,
    const float* __restrict__ b2, const float* __restrict__ root,
    const float* __restrict__ nn_bias,
    int c, int nK2, int nK1, int dnK1, int dnK2, int dnRd)
{
    __shared__ __align__(16) unsigned char sm[(128 + 32) * AS_STRIDE * 2];
    int b = blockIdx.x;
    if (b < nK2) {
        k2_role(sm, b, c - 1, dnK2);
    } else if (b < nK2 + nK1) {
        k1_role(sm, b - nK2, nK1, x, ea, c, dnK1);
    } else {
        red_role(b - nK2 - nK1, c - 2, dnRd, b2, x, root, nn_bias);
    }
}

// ---------------- K3: xw = x1 @ gcn_w ----------------
__global__ void k3_xw(const float* __restrict__ gcn_w) {
    int gid = blockIdx.x * blockDim.x + threadIdx.x;
    if (gid >= NN * 32) return;
    int d = gid >> 5, o = gid & 31;
    float acc = 0.f;
    #pragma unroll
    for (int c = 0; c < 32; ++c)
        acc = fmaf(g_x1[d * 32 + c], gcn_w[c * 32 + o], acc);
    g_xw[gid] = acc;
}

// ---------------- K4: GCN aggregate via CSR (warp per dst) ----------------
__global__ void k4_gcn(const float* __restrict__ gcn_b) {
    int wid = (blockIdx.x * blockDim.x + threadIdx.x) >> 5;
    int lane = threadIdx.x & 31;
    int nwarps = (gridDim.x * blockDim.x) >> 5;
    for (int d = wid; d < NN; d += nwarps) {
        float dd = g_dis[d];
        float acc = 0.f;
        int beg = g_offs[d], end = g_offs[d + 1];
        for (int j = beg; j < end; ++j) {
            int e = g_elist[j];
            int s = g_src[e];
            acc = fmaf(g_dis[s], g_xw[s * 32 + lane], acc);
        }
        g_x2[d * 32 + lane] = gcn_b[lane] + dd * (dd * g_xw[d * 32 + lane] + acc);
    }
}

// ---------------- K5: edge scorer ----------------
__global__ void k5_score(const float* __restrict__ lin_w, const float* __restrict__ lin_b,
                         float* __restrict__ out) {
    int e = blockIdx.x * blockDim.x + threadIdx.x;
    if (e >= EE) return;
    int s = g_src[e], d = g_dst[e];
    const float4* a = (const float4*)(g_x2 + (size_t)s * 32);
    const float4* b = (const float4*)(g_x2 + (size_t)d * 32);
    const float4* w = (const float4*)lin_w;
    float acc = lin_b[0];
    #pragma unroll
    for (int q = 0; q < 8; ++q) {
        float4 av = a[q], wv = w[q];
        acc += av.x * wv.x + av.y * wv.y + av.z * wv.z + av.w * wv.w;
    }
    #pragma unroll
    for (int q = 0; q < 8; ++q) {
        float4 bv = b[q], wv = w[8 + q];
        acc += bv.x * wv.x + bv.y * wv.y + bv.z * wv.z + bv.w * wv.w;
    }
    out[e] = 1.f / (1.f + expf(-acc));
}

// ---------------- launch ----------------
static inline int dn_of(int c) {
    if (c < 0 || c >= NCHUNK) return 0;
    int d0 = c * CH;
    int dn = NN - d0;
    if (dn > CH) dn = CH;
    return dn > 0 ? dn : 0;
}

extern "C" void kernel_launch(void* const* d_in, const int* in_sizes, int n_in,
                              void* d_out, int out_size) {
    const float* x       = (const float*)d_in[0];
    const void*  ei      = d_in[1];
    const float* ea      = (const float*)d_in[2];
    const float* w1      = (const float*)d_in[3];
    const float* b1      = (const float*)d_in[4];
    const float* w2      = (const float*)d_in[5];
    const float* b2      = (const float*)d_in[6];
    const float* root    = (const float*)d_in[7];
    const float* nn_bias = (const float*)d_in[8];
    const float* gcn_w   = (const float*)d_in[9];
    const float* gcn_b   = (const float*)d_in[10];
    const float* lin_w   = (const float*)d_in[11];
    const float* lin_b   = (const float*)d_in[12];
    float*       out     = (float*)d_out;

    k_dz<<<(NN + 255) / 256, 256>>>(ei);
    k_prep<<<(EE + 255) / 256, 256>>>(ei);
    k_scan<<<1, 1024>>>();
    k_scatter<<<(EE + 255) / 256, 256>>>();
    k_wpack<<<(32 * SROW + 255) / 256, 256>>>(w2, w1, b1);

    // software pipeline: combo(c) = k2(c-1) || k1(c) || reduce(c-2)
    for (int c = 0; c <= NCHUNK + 1; ++c) {
        int dnK1 = dn_of(c);
        int dnK2 = dn_of(c - 1);
        int dnRd = dn_of(c - 2);
        int nK2 = dnK2 ? ((dnK2 + 127) / 128) * JSLICE : 0;
        int nK1 = dnK1 ? (dnK1 < K1GRID ? dnK1 : K1GRID) : 0;
        int nRd = dnRd ? (dnRd * 32 + 255) / 256 : 0;
        int grid = nK2 + nK1 + nRd;
        if (grid > 0)
            k_combo<<<grid, 256>>>(x, ea, b2, root, nn_bias, c, nK2, nK1, dnK1, dnK2, dnRd);
    }

    k3_xw<<<(NN * 32 + 255) / 256, 256>>>(gcn_w);
    k4_gcn<<<512, 256>>>(gcn_b);
    k5_score<<<(EE + 255) / 256, 256>>>(lin_w, lin_b, out);
}

// round 12
// speedup vs baseline: 1.1344x; 1.0021x over previous
#include <cuda_runtime.h>
#include <cuda_fp16.h>
#include <math.h>

#define NN 50000
#define EE 400000
#define IN_CH 16
#define HID 32
#define KDIM 512          // HID*IN_CH
#define SROW 8192         // KDIM*IN_CH
#define CH 2560           // dst-chunk size
#define NCHUNK 20
#define JSLICE 8
#define JLEN 1024         // SROW / JSLICE
#define K1GRID 2048
#define AS_STRIDE 72

// ---------------- scratch (static device globals; no allocations) ----------------
__device__ __half  g_Sh[2][(size_t)CH * SROW];   // double-buffered S, 2 x 42 MB
__device__ float   g_P[2][JSLICE * CH * 32];     // double-buffered partials
__device__ __half  g_pk[(size_t)EE * 32];        // dst-sorted payload: [ea fp16 x16 | x fp16 x16]
__device__ __half  g_w2t[32 * SROW];
__device__ __half2 g_w1h[256 * 16];
__device__ __half2 g_b1h[256];
__device__ float   g_Xsum[NN * 16];
__device__ float   g_x1[NN * 32];
__device__ float   g_xw[NN * 32];
__device__ float   g_x2[NN * 32];
__device__ float   g_dis[NN];
__device__ int     g_cnt[NN];
__device__ int     g_offs[NN + 1];
__device__ int     g_cursor[NN];
__device__ int     g_elist[EE];
__device__ int     g_src[EE];
__device__ int     g_dst[EE];
__device__ int     g_is64;

// ---------------- [0] detect dtype + zero counters + pack weights ----------------
__global__ void k_dzw(const void* __restrict__ ei, const float* __restrict__ w2,
                      const float* __restrict__ w1, const float* __restrict__ b1) {
    int idx = blockIdx.x * blockDim.x + threadIdx.x;
    if (idx < NN) g_cnt[idx] = 0;
    if (idx == 0) {
        const long long* p = (const long long*)ei;
        int ok = 1;
        #pragma unroll
        for (int q = 0; q < 16; ++q) {
            long long v = p[q];
            if (v < 0 || v >= NN) ok = 0;
        }
        g_is64 = ok;
    }
    if (idx < 32 * SROW) {
        int o  = idx >> 13;
        int jp = idx & (SROW - 1);
        int tt = jp >> 5;
        int r  = jp & 31;
        int i  = r >> 1;
        int c  = r & 1;
        int k  = 2 * tt + c;
        g_w2t[idx] = __float2half(w2[(size_t)k * KDIM + i * 32 + o]);
    }
    if (idx < 256 * 16) {
        int t = idx >> 4, i = idx & 15;
        g_w1h[idx] = __floats2half2_rn(w1[i * KDIM + 2 * t], w1[i * KDIM + 2 * t + 1]);
    }
    if (idx < 256)
        g_b1h[idx] = __floats2half2_rn(b1[2 * idx], b1[2 * idx + 1]);
}

// ---------------- [1] decode edges + histogram ----------------
__global__ void k_prep(const void* __restrict__ ei) {
    int e = blockIdx.x * blockDim.x + threadIdx.x;
    if (e >= EE) return;
    int s, d;
    if (g_is64) {
        s = (int)((const long long*)ei)[e];
        d = (int)((const long long*)ei)[EE + e];
    } else {
        s = ((const int*)ei)[e];
        d = ((const int*)ei)[EE + e];
    }
    s = s < 0 ? 0 : (s >= NN ? NN - 1 : s);
    d = d < 0 ? 0 : (d >= NN ? NN - 1 : d);
    g_src[e] = s;
    g_dst[e] = d;
    atomicAdd(&g_cnt[d], 1);
}

// ---------------- [2] one-pass block scan (+ degree norms) ----------------
#define SCAN_PER 49
__global__ void k_scan() {
    __shared__ int wsum[32];
    int t = threadIdx.x, lane = t & 31, w = t >> 5;
    int base = t * SCAN_PER;
    int sum = 0;
    #pragma unroll 7
    for (int i = 0; i < SCAN_PER; ++i) {
        int idx = base + i;
        if (idx < NN) sum += g_cnt[idx];
    }
    int inc = sum;
    #pragma unroll
    for (int off = 1; off < 32; off <<= 1) {
        int y = __shfl_up_sync(0xffffffffu, inc, off);
        if (lane >= off) inc += y;
    }
    if (lane == 31) wsum[w] = inc;
    __syncthreads();
    if (w == 0) {
        int s = wsum[lane];
        #pragma unroll
        for (int off = 1; off < 32; off <<= 1) {
            int y = __shfl_up_sync(0xffffffffu, s, off);
            if (lane >= off) s += y;
        }
        wsum[lane] = s;
    }
    __syncthreads();
    int run = inc - sum + (w > 0 ? wsum[w - 1] : 0);
    #pragma unroll 7
    for (int i = 0; i < SCAN_PER; ++i) {
        int idx = base + i;
        if (idx < NN) {
            int v = g_cnt[idx];
            g_offs[idx]   = run;
            g_cursor[idx] = run;
            g_dis[idx]    = rsqrtf((float)(v + 1));
            run += v;
        }
    }
    if (t == 0) g_offs[NN] = EE;
}

// ---------------- [3] scatter edges into dst-CSR ----------------
__global__ void k_scatter() {
    int e = blockIdx.x * blockDim.x + threadIdx.x;
    if (e >= EE) return;
    int pos = atomicAdd(&g_cursor[g_dst[e]], 1);
    if (pos >= 0 && pos < EE) g_elist[pos] = e;
}

// ---------------- [4] build contiguous dst-sorted payload ----------------
// g_pk[p][j] : j<16 -> fp16(ea[e][j]) ; j>=16 -> fp16(x[src[e]][j-16])
__global__ void k_pack(const float* __restrict__ x, const float* __restrict__ ea) {
    int gid = blockIdx.x * blockDim.x + threadIdx.x;
    if (gid >= EE * 32) return;
    int p = gid >> 5;
    int j = gid & 31;
    int e = g_elist[p];
    float v;
    if (j < 16) v = ea[(size_t)e * 16 + j];
    else        v = x[(size_t)g_src[e] * 16 + (j - 16)];
    g_pk[(size_t)p * 32 + j] = __float2half(v);
}

// ================= combo roles =================

// --- role A: K1 build S rows for chunk cc into g_Sh[cc&1] (prefetched stream) ---
__device__ __forceinline__ void k1_role(
    unsigned char* sm, int bid, int ngrid, int cc, int dn)
{
    int t = threadIdx.x;
    __half* Sbuf = g_Sh[cc & 1];
    int d0 = cc * CH;

    __half2 w1h[16];
    #pragma unroll
    for (int q = 0; q < 4; ++q)
        *(uint4*)&w1h[4 * q] = ((const uint4*)(g_w1h + t * 16))[q];
    __half2 b1h = g_b1h[t];
    const __half2 hz = __float2half2_rn(0.f);

    __half2 (*pay)[32] = (__half2(*)[32])sm;   // [16 edges][32 dup-half2] = 2 KB

    int slot = t >> 4;          // edge slot this thread stages
    int jo   = (t & 15) * 2;    // element pair

    int dl = bid;
    int nbeg = 0, nend = 0;
    if (dl < dn) { nbeg = g_offs[d0 + dl]; nend = g_offs[d0 + dl + 1]; }
    unsigned pf = 0;
    int pfpos = -1;
    if (dl < dn && nend > nbeg) {
        pfpos = nbeg;
        if (slot < nend - nbeg)
            pf = *(const unsigned*)(g_pk + ((size_t)(nbeg + slot) * 32 + jo));
    }

    while (dl < dn) {
        int beg = nbeg, end = nend;
        int dl2 = dl + ngrid;
        if (dl2 < dn) { nbeg = g_offs[d0 + dl2]; nend = g_offs[d0 + dl2 + 1]; }
        else          { nbeg = 0; nend = 0; }

        __half2 S[16];
        #pragma unroll
        for (int i = 0; i < 16; ++i) S[i] = hz;
        float xsum = 0.f;

        for (int base = beg; base < end; base += 16) {
            if (pfpos != base) {   // rare sync fallback (after zero-degree dst)
                if (slot < end - base)
                    pf = *(const unsigned*)(g_pk + ((size_t)(base + slot) * 32 + jo));
            }
            __syncthreads();
            {
                __half2 two = *reinterpret_cast<__half2*>(&pf);
                uint2 d2;
                __half2 dl_ = __half2half2(__low2half(two));
                __half2 dh_ = __half2half2(__high2half(two));
                d2.x = *reinterpret_cast<unsigned*>(&dl_);
                d2.y = *reinterpret_cast<unsigned*>(&dh_);
                *(uint2*)&pay[slot][jo] = d2;
            }
            __syncthreads();
            // prefetch next batch (next 16 positions, or next dst's first batch)
            int nb = base + 16;
            int pbeg, lim2;
            if (nb < end) { pbeg = nb;   lim2 = end - nb; }
            else          { pbeg = nbeg; lim2 = nend - nbeg; }
            if (lim2 > 0) {
                pfpos = pbeg;
                if (slot < lim2)
                    pf = *(const unsigned*)(g_pk + ((size_t)(pbeg + slot) * 32 + jo));
            } else pfpos = -1;

            int nc = end - base; if (nc > 16) nc = 16;
            for (int c = 0; c < nc; ++c) {
                __half2 er[16], xr[16];
                #pragma unroll
                for (int q = 0; q < 4; ++q) {
                    *(uint4*)&er[4 * q] = *(const uint4*)&pay[c][4 * q];
                    *(uint4*)&xr[4 * q] = *(const uint4*)&pay[c][16 + 4 * q];
                }
                __half2 rh = b1h;
                #pragma unroll
                for (int i = 0; i < 16; ++i)
                    rh = __hfma2(er[i], w1h[i], rh);
                rh = __hmax2(rh, hz);
                #pragma unroll
                for (int i = 0; i < 16; ++i)
                    S[i] = __hfma2(rh, xr[i], S[i]);
                if (t < 16) xsum += __low2float(pay[c][16 + t]);
            }
        }
        uint4* Sp = (uint4*)(Sbuf + (size_t)dl * SROW + t * 32);
        #pragma unroll
        for (int q = 0; q < 4; ++q) Sp[q] = ((const uint4*)S)[q];
        if (t < 16) g_Xsum[(d0 + dl) * 16 + t] = xsum;
        dl = dl2;
    }
}

// --- role B: K2 MMA over a j-slice for chunk cc ---
__device__ __forceinline__ void k2_role(unsigned char* sm, int bid, int cc, int dn)
{
    __half* As = (__half*)sm;
    __half* Bs = (__half*)(sm + 128 * AS_STRIDE * 2);
    const __half* Sbuf = g_Sh[cc & 1];
    float* Pbuf = g_P[cc & 1];

    int tid  = threadIdx.x;
    int warp = tid >> 5;
    int lane = tid & 31;
    int g    = lane >> 2;
    int t4   = lane & 3;
    int slice = bid & (JSLICE - 1);
    int r0    = (bid >> 3) * 128;
    int jbase = slice * JLEN;

    float c0[4], c1[4], c2[4], c3[4];
    #pragma unroll
    for (int nt = 0; nt < 4; ++nt) { c0[nt] = 0.f; c1[nt] = 0.f; c2[nt] = 0.f; c3[nt] = 0.f; }

    for (int it = 0; it < JLEN / 64; ++it) {
        int j0 = jbase + it * 64;
        __syncthreads();
        #pragma unroll
        for (int u = 0; u < 4; ++u) {
            int idx = tid + u * 256;
            int row = idx >> 3;
            int q   = idx & 7;
            int rl  = r0 + row; if (rl >= dn) rl = dn - 1;
            *(uint4*)&As[row * AS_STRIDE + q * 8] =
                ((const uint4*)(Sbuf + (size_t)rl * SROW + j0))[q];
        }
        {
            int row = tid >> 3;
            int q   = tid & 7;
            *(uint4*)&Bs[row * AS_STRIDE + q * 8] =
                ((const uint4*)(g_w2t + (size_t)row * SROW + j0))[q];
        }
        __syncthreads();

        #pragma unroll
        for (int kk = 0; kk < 64; kk += 16) {
            unsigned a0 = *(const unsigned*)&As[(warp * 16 + g    ) * AS_STRIDE + kk     + 2 * t4];
            unsigned a1 = *(const unsigned*)&As[(warp * 16 + g + 8) * AS_STRIDE + kk     + 2 * t4];
            unsigned a2 = *(const unsigned*)&As[(warp * 16 + g    ) * AS_STRIDE + kk + 8 + 2 * t4];
            unsigned a3 = *(const unsigned*)&As[(warp * 16 + g + 8) * AS_STRIDE + kk + 8 + 2 * t4];
            #pragma unroll
            for (int nt = 0; nt < 4; ++nt) {
                unsigned b0 = *(const unsigned*)&Bs[(nt * 8 + g) * AS_STRIDE + kk     + 2 * t4];
                unsigned b1 = *(const unsigned*)&Bs[(nt * 8 + g) * AS_STRIDE + kk + 8 + 2 * t4];
                asm volatile(
                    "mma.sync.aligned.m16n8k16.row.col.f32.f16.f16.f32 "
                    "{%0,%1,%2,%3}, {%4,%5,%6,%7}, {%8,%9}, {%0,%1,%2,%3};"
                    : "+f"(c0[nt]), "+f"(c1[nt]), "+f"(c2[nt]), "+f"(c3[nt])
                    : "r"(a0), "r"(a1), "r"(a2), "r"(a3), "r"(b0), "r"(b1));
            }
        }
    }

    #pragma unroll
    for (int nt = 0; nt < 4; ++nt) {
        int row = r0 + warp * 16 + g;
        int col = nt * 8 + 2 * t4;
        if (row < dn)
            *(float2*)&Pbuf[((size_t)slice * CH + row) * 32 + col] = make_float2(c0[nt], c1[nt]);
        if (row + 8 < dn)
            *(float2*)&Pbuf[((size_t)slice * CH + row + 8) * 32 + col] = make_float2(c2[nt], c3[nt]);
    }
}

// --- role C: reduce partials + NNConv epilogue for chunk cc ---
__device__ __forceinline__ void red_role(
    int bid, int cc, int dn,
    const float* __restrict__ b2, const float* __restrict__ x,
    const float* __restrict__ root, const float* __restrict__ nn_bias)
{
    int gid = bid * 256 + threadIdx.x;
    if (gid >= dn * 32) return;
    const float* Pbuf = g_P[cc & 1];
    int rl = gid >> 5, o = gid & 31;
    int d = cc * CH + rl;
    float v = nn_bias[o];
    #pragma unroll
    for (int s = 0; s < JSLICE; ++s)
        v += Pbuf[((size_t)s * CH + rl) * 32 + o];
    #pragma unroll
    for (int i = 0; i < 16; ++i)
        v = fmaf(g_Xsum[d * 16 + i], b2[i * 32 + o], v);
    #pragma unroll
    for (int c = 0; c < 16; ++c)
        v = fmaf(x[(size_t)d * 16 + c], root[c * 32 + o], v);
    g_x1[d * 32 + o] = fmaxf(v, 0.f);
}

// --- combo: block ranges -> roles (no intra-launch dependencies) ---
__global__ __launch_bounds__(256) void k_combo(
    const float* __restrict__ x,
    const float* __restrict__ b2, const float* __restrict__ root,
    const float* __restrict__ nn_bias,
    int c, int nK2, int nK1, int dnK1, int dnK2, int dnRd)
{
    __shared__ __align__(16) unsigned char sm[(128 + 32) * AS_STRIDE * 2];
    int b = blockIdx.x;
    if (b < nK2) {
        k2_role(sm, b, c - 1, dnK2);
    } else if (b < nK2 + nK1) {
        k1_role(sm, b - nK2, nK1, c, dnK1);
    } else {
        red_role(b - nK2 - nK1, c - 2, dnRd, b2, x, root, nn_bias);
    }
}

// ---------------- K3: xw = x1 @ gcn_w ----------------
__global__ void k3_xw(const float* __restrict__ gcn_w) {
    int gid = blockIdx.x * blockDim.x + threadIdx.x;
    if (gid >= NN * 32) return;
    int d = gid >> 5, o = gid & 31;
    float acc = 0.f;
    #pragma unroll
    for (int c = 0; c < 32; ++c)
        acc = fmaf(g_x1[d * 32 + c], gcn_w[c * 32 + o], acc);
    g_xw[gid] = acc;
}

// ---------------- K4: GCN aggregate via CSR (warp per dst) ----------------
__global__ void k4_gcn(const float* __restrict__ gcn_b) {
    int wid = (blockIdx.x * blockDim.x + threadIdx.x) >> 5;
    int lane = threadIdx.x & 31;
    int nwarps = (gridDim.x * blockDim.x) >> 5;
    for (int d = wid; d < NN; d += nwarps) {
        float dd = g_dis[d];
        float acc = 0.f;
        int beg = g_offs[d], end = g_offs[d + 1];
        for (int j = beg; j < end; ++j) {
            int e = g_elist[j];
            int s = g_src[e];
            acc = fmaf(g_dis[s], g_xw[s * 32 + lane], acc);
        }
        g_x2[d * 32 + lane] = gcn_b[lane] + dd * (dd * g_xw[d * 32 + lane] + acc);
    }
}

// ---------------- K5: edge scorer ----------------
__global__ void k5_score(const float* __restrict__ lin_w, const float* __restrict__ lin_b,
                         float* __restrict__ out) {
    int e = blockIdx.x * blockDim.x + threadIdx.x;
    if (e >= EE) return;
    int s = g_src[e], d = g_dst[e];
    const float4* a = (const float4*)(g_x2 + (size_t)s * 32);
    const float4* b = (const float4*)(g_x2 + (size_t)d * 32);
    const float4* w = (const float4*)lin_w;
    float acc = lin_b[0];
    #pragma unroll
    for (int q = 0; q < 8; ++q) {
        float4 av = a[q], wv = w[q];
        acc += av.x * wv.x + av.y * wv.y + av.z * wv.z + av.w * wv.w;
    }
    #pragma unroll
    for (int q = 0; q < 8; ++q) {
        float4 bv = b[q], wv = w[8 + q];
        acc += bv.x * wv.x + bv.y * wv.y + bv.z * wv.z + bv.w * wv.w;
    }
    out[e] = 1.f / (1.f + expf(-acc));
}

// ---------------- launch ----------------
static inline int dn_of(int c) {
    if (c < 0 || c >= NCHUNK) return 0;
    int d0 = c * CH;
    int dn = NN - d0;
    if (dn > CH) dn = CH;
    return dn > 0 ? dn : 0;
}

extern "C" void kernel_launch(void* const* d_in, const int* in_sizes, int n_in,
                              void* d_out, int out_size) {
    const float* x       = (const float*)d_in[0];
    const void*  ei      = d_in[1];
    const float* ea      = (const float*)d_in[2];
    const float* w1      = (const float*)d_in[3];
    const float* b1      = (const float*)d_in[4];
    const float* w2      = (const float*)d_in[5];
    const float* b2      = (const float*)d_in[6];
    const float* root    = (const float*)d_in[7];
    const float* nn_bias = (const float*)d_in[8];
    const float* gcn_w   = (const float*)d_in[9];
    const float* gcn_b   = (const float*)d_in[10];
    const float* lin_w   = (const float*)d_in[11];
    const float* lin_b   = (const float*)d_in[12];
    float*       out     = (float*)d_out;

    k_dzw<<<(32 * SROW + 255) / 256, 256>>>(ei, w2, w1, b1);
    k_prep<<<(EE + 255) / 256, 256>>>(ei);
    k_scan<<<1, 1024>>>();
    k_scatter<<<(EE + 255) / 256, 256>>>();
    k_pack<<<(EE * 32 + 255) / 256, 256>>>(x, ea);

    // software pipeline: combo(c) = k2(c-1) || k1(c) || reduce(c-2)
    for (int c = 0; c <= NCHUNK + 1; ++c) {
        int dnK1 = dn_of(c);
        int dnK2 = dn_of(c - 1);
        int dnRd = dn_of(c - 2);
        int nK2 = dnK2 ? ((dnK2 + 127) / 128) * JSLICE : 0;
        int nK1 = dnK1 ? (dnK1 < K1GRID ? dnK1 : K1GRID) : 0;
        int nRd = dnRd ? (dnRd * 32 + 255) / 256 : 0;
        int grid = nK2 + nK1 + nRd;
        if (grid > 0)
            k_combo<<<grid, 256>>>(x, b2, root, nn_bias, c, nK2, nK1, dnK1, dnK2, dnRd);
    }

    k3_xw<<<(NN * 32 + 255) / 256, 256>>>(gcn_w);
    k4_gcn<<<512, 256>>>(gcn_b);
    k5_score<<<(EE + 255) / 256, 256>>>(lin_w, lin_b, out);
}

// round 14
// speedup vs baseline: 1.4649x; 1.2913x over previous
#include <cuda_runtime.h>
#include <cuda_fp16.h>
#include <math.h>

#define NN 50000
#define EE 400000
#define IN_CH 16
#define HID 32
#define KDIM 512          // HID*IN_CH
#define SROW 8192         // KDIM*IN_CH
#define CH 2560           // dst-chunk size
#define NCHUNK 20
#define JSLICE 8
#define JLEN 1024         // SROW / JSLICE
#define K1GRID 2048
#define AS_STRIDE 72

// ---------------- scratch (static device globals; no allocations) ----------------
__device__ __half  g_Sh[2][(size_t)CH * SROW];   // double-buffered S, 2 x 42 MB
__device__ float   g_P[2][JSLICE * CH * 32];     // double-buffered partials
__device__ __half  g_pk[(size_t)EE * 32];        // dst-sorted payload: [ea fp16 x16 | x fp16 x16]
__device__ __half  g_w2t[32 * SROW];             // w2 permuted to S-fragment layout
__device__ unsigned g_w1f[8 * 4 * 4 * 32];       // w1 A-fragments: [warp][mtile][q][lane]
__device__ float   g_Xsum[NN * 16];
__device__ float   g_x1[NN * 32];
__device__ float   g_xw[NN * 32];
__device__ float   g_x2[NN * 32];
__device__ float   g_dis[NN];
__device__ int     g_cnt[NN];
__device__ int     g_offs[NN + 1];
__device__ int     g_cursor[NN];
__device__ int     g_elist[EE];
__device__ int     g_src[EE];
__device__ int     g_dst[EE];
__device__ int     g_is64;

// ---------------- [0] detect dtype + zero counters + pack weights ----------------
__global__ void k_dzw(const void* __restrict__ ei, const float* __restrict__ w2,
                      const float* __restrict__ w1) {
    int idx = blockIdx.x * blockDim.x + threadIdx.x;
    if (idx < NN) g_cnt[idx] = 0;
    if (idx == 0) {
        const long long* p = (const long long*)ei;
        int ok = 1;
        #pragma unroll
        for (int q = 0; q < 16; ++q) {
            long long v = p[q];
            if (v < 0 || v >= NN) ok = 0;
        }
        g_is64 = ok;
    }
    // w2t in the S-fragment contraction order:
    // jp = u*2 + h ; u -> w,m,rh,g,t4,n ; K = 64w+16m+8rh+g ; i = 8n+2t4+h
    if (idx < 32 * SROW) {
        int o  = idx >> 13;
        int jp = idx & (SROW - 1);
        int u = jp >> 1, h = jp & 1;
        int w  = u >> 9;
        int m  = (u >> 7) & 3;
        int rh = (u >> 6) & 1;
        int gg = (u >> 3) & 7;
        int t4 = (u >> 1) & 3;
        int n  = u & 1;
        int K  = 64 * w + 16 * m + 8 * rh + gg;
        int i  = 8 * n + 2 * t4 + h;
        g_w2t[idx] = __float2half(w2[(size_t)K * KDIM + i * 32 + o]);
    }
    // w1 A-fragments (m16k16, row = k, col = i)
    if (idx < 4096) {
        int w = idx >> 9, m = (idx >> 7) & 3, q = (idx >> 5) & 3, l = idx & 31;
        int gg = l >> 2, t4 = l & 3;
        int K  = 64 * w + 16 * m + gg + ((q & 1) << 3);
        int i0 = 2 * t4 + ((q >> 1) << 3);
        __half2 hv = __floats2half2_rn(w1[i0 * KDIM + K], w1[(i0 + 1) * KDIM + K]);
        g_w1f[idx] = *(unsigned*)&hv;
    }
}

// ---------------- [1] decode edges + histogram ----------------
__global__ void k_prep(const void* __restrict__ ei) {
    int e = blockIdx.x * blockDim.x + threadIdx.x;
    if (e >= EE) return;
    int s, d;
    if (g_is64) {
        s = (int)((const long long*)ei)[e];
        d = (int)((const long long*)ei)[EE + e];
    } else {
        s = ((const int*)ei)[e];
        d = ((const int*)ei)[EE + e];
    }
    s = s < 0 ? 0 : (s >= NN ? NN - 1 : s);
    d = d < 0 ? 0 : (d >= NN ? NN - 1 : d);
    g_src[e] = s;
    g_dst[e] = d;
    atomicAdd(&g_cnt[d], 1);
}

// ---------------- [2] one-pass block scan (+ degree norms) ----------------
#define SCAN_PER 49
__global__ void k_scan() {
    __shared__ int wsum[32];
    int t = threadIdx.x, lane = t & 31, w = t >> 5;
    int base = t * SCAN_PER;
    int sum = 0;
    #pragma unroll 7
    for (int i = 0; i < SCAN_PER; ++i) {
        int idx = base + i;
        if (idx < NN) sum += g_cnt[idx];
    }
    int inc = sum;
    #pragma unroll
    for (int off = 1; off < 32; off <<= 1) {
        int y = __shfl_up_sync(0xffffffffu, inc, off);
        if (lane >= off) inc += y;
    }
    if (lane == 31) wsum[w] = inc;
    __syncthreads();
    if (w == 0) {
        int s = wsum[lane];
        #pragma unroll
        for (int off = 1; off < 32; off <<= 1) {
            int y = __shfl_up_sync(0xffffffffu, s, off);
            if (lane >= off) s += y;
        }
        wsum[lane] = s;
    }
    __syncthreads();
    int run = inc - sum + (w > 0 ? wsum[w - 1] : 0);
    #pragma unroll 7
    for (int i = 0; i < SCAN_PER; ++i) {
        int idx = base + i;
        if (idx < NN) {
            int v = g_cnt[idx];
            g_offs[idx]   = run;
            g_cursor[idx] = run;
            g_dis[idx]    = rsqrtf((float)(v + 1));
            run += v;
        }
    }
    if (t == 0) g_offs[NN] = EE;
}

// ---------------- [3] scatter edges into dst-CSR ----------------
__global__ void k_scatter() {
    int e = blockIdx.x * blockDim.x + threadIdx.x;
    if (e >= EE) return;
    int pos = atomicAdd(&g_cursor[g_dst[e]], 1);
    if (pos >= 0 && pos < EE) g_elist[pos] = e;
}

// ---------------- [4] build contiguous dst-sorted payload ----------------
__global__ void k_pack(const float* __restrict__ x, const float* __restrict__ ea) {
    int gid = blockIdx.x * blockDim.x + threadIdx.x;
    if (gid >= EE * 32) return;
    int p = gid >> 5;
    int j = gid & 31;
    int e = g_elist[p];
    float v;
    if (j < 16) v = ea[(size_t)e * 16 + j];
    else        v = x[(size_t)g_src[e] * 16 + (j - 16)];
    g_pk[(size_t)p * 32 + j] = __float2half(v);
}

// ================= combo roles =================

// --- role A: K1 via tensor cores. Warp w owns k in [64w, 64w+64). ---
__device__ __forceinline__ void k1_role(
    unsigned char* sm, int bid, int ngrid, int cc, int dn,
    const float* __restrict__ b1)
{
    int t = threadIdx.x;
    int w = t >> 5, lane = t & 31, gg = lane >> 2, t4 = lane & 3;
    __half* Sbuf = g_Sh[cc & 1];
    int d0 = cc * CH;

    unsigned w1f[4][4];
    #pragma unroll
    for (int m = 0; m < 4; ++m)
        #pragma unroll
        for (int q = 0; q < 4; ++q)
            w1f[m][q] = g_w1f[((w * 4 + m) * 4 + q) * 32 + lane];
    unsigned biasL[4], biasH[4];
    #pragma unroll
    for (int m = 0; m < 4; ++m) {
        int K = 64 * w + 16 * m + gg;
        __half2 hl = __float2half2_rn(b1[K]);
        __half2 hh = __float2half2_rn(b1[K + 8]);
        biasL[m] = *(unsigned*)&hl;
        biasH[m] = *(unsigned*)&hh;
    }
    const __half2 hz2 = __float2half2_rn(0.f);

    // payload smem: ea 16 rows x 48B (32B used), x same at +768
    unsigned* ea_u = (unsigned*)sm;
    unsigned* x_u  = (unsigned*)(sm + 768);
    __half*   x_h  = (__half*)(sm + 768);

    int tI = lane >> 3, r = lane & 7;
    unsigned ea_ld = (unsigned)__cvta_generic_to_shared(
        sm + ((tI & 2) ? (8 + r) : r) * 48 + ((tI & 1) ? 16 : 0));
    unsigned x_ld = (unsigned)__cvta_generic_to_shared(
        sm + 768 + ((tI & 1) ? (8 + r) : r) * 48 + ((tI & 2) ? 16 : 0));

    int slot = t >> 4;
    int jj   = t & 15;

    int dl = bid;
    int nbeg = 0, nend = 0;
    if (dl < dn) { nbeg = g_offs[d0 + dl]; nend = g_offs[d0 + dl + 1]; }
    unsigned pf = 0;
    int pfpos = -1;
    if (dl < dn && nend > nbeg) {
        pfpos = nbeg;
        if (slot < nend - nbeg)
            pf = *(const unsigned*)(g_pk + ((size_t)(nbeg + slot) * 32 + jj * 2));
    }

    while (dl < dn) {
        int beg = nbeg, end = nend;
        int dl2 = dl + ngrid;
        if (dl2 < dn) { nbeg = g_offs[d0 + dl2]; nend = g_offs[d0 + dl2 + 1]; }
        else          { nbeg = 0; nend = 0; }

        float Sacc[4][2][4];
        #pragma unroll
        for (int m = 0; m < 4; ++m)
            #pragma unroll
            for (int n = 0; n < 2; ++n)
                #pragma unroll
                for (int q = 0; q < 4; ++q) Sacc[m][n][q] = 0.f;
        float xsum = 0.f;

        for (int base = beg; base < end; base += 16) {
            int nc = end - base; if (nc > 16) nc = 16;
            if (pfpos != base) {
                if (slot < nc)
                    pf = *(const unsigned*)(g_pk + ((size_t)(base + slot) * 32 + jj * 2));
            }
            __syncthreads();
            {
                unsigned v = (slot < nc) ? pf : 0u;
                if (jj < 8) ea_u[slot * 12 + jj] = v;
                else        x_u[slot * 12 + (jj - 8)] = v;
            }
            __syncthreads();
            // prefetch next batch
            {
                int nb = base + 16;
                int pbeg, lim2;
                if (nb < end) { pbeg = nb;   lim2 = end - nb; }
                else          { pbeg = nbeg; lim2 = nend - nbeg; }
                if (lim2 > 0) {
                    pfpos = pbeg;
                    if (slot < lim2)
                        pf = *(const unsigned*)(g_pk + ((size_t)(pbeg + slot) * 32 + jj * 2));
                } else pfpos = -1;
            }

            unsigned bea0, bea1, bea2, bea3, bx0, bx1, bx2, bx3;
            asm volatile("ldmatrix.sync.aligned.m8n8.x4.shared.b16 {%0,%1,%2,%3}, [%4];"
                         : "=r"(bea0), "=r"(bea1), "=r"(bea2), "=r"(bea3) : "r"(ea_ld));
            asm volatile("ldmatrix.sync.aligned.m8n8.x4.trans.shared.b16 {%0,%1,%2,%3}, [%4];"
                         : "=r"(bx0), "=r"(bx1), "=r"(bx2), "=r"(bx3) : "r"(x_ld));

            if (t < 16) {
                for (int c = 0; c < nc; ++c)
                    xsum += __half2float(x_h[c * 24 + t]);
            }

            #pragma unroll
            for (int m = 0; m < 4; ++m) {
                unsigned r0, r1, r2, r3;
                asm volatile(
                    "mma.sync.aligned.m16n8k16.row.col.f16.f16.f16.f16 "
                    "{%0,%1}, {%2,%3,%4,%5}, {%6,%7}, {%8,%9};"
                    : "=r"(r0), "=r"(r1)
                    : "r"(w1f[m][0]), "r"(w1f[m][1]), "r"(w1f[m][2]), "r"(w1f[m][3]),
                      "r"(bea0), "r"(bea1), "r"(biasL[m]), "r"(biasH[m]));
                asm volatile(
                    "mma.sync.aligned.m16n8k16.row.col.f16.f16.f16.f16 "
                    "{%0,%1}, {%2,%3,%4,%5}, {%6,%7}, {%8,%9};"
                    : "=r"(r2), "=r"(r3)
                    : "r"(w1f[m][0]), "r"(w1f[m][1]), "r"(w1f[m][2]), "r"(w1f[m][3]),
                      "r"(bea2), "r"(bea3), "r"(biasL[m]), "r"(biasH[m]));
                // relu
                { __half2* p = (__half2*)&r0; *p = __hmax2(*p, hz2); }
                { __half2* p = (__half2*)&r1; *p = __hmax2(*p, hz2); }
                { __half2* p = (__half2*)&r2; *p = __hmax2(*p, hz2); }
                { __half2* p = (__half2*)&r3; *p = __hmax2(*p, hz2); }
                // GEMM2: S += r @ x
                asm volatile(
                    "mma.sync.aligned.m16n8k16.row.col.f32.f16.f16.f32 "
                    "{%0,%1,%2,%3}, {%4,%5,%6,%7}, {%8,%9}, {%0,%1,%2,%3};"
                    : "+f"(Sacc[m][0][0]), "+f"(Sacc[m][0][1]), "+f"(Sacc[m][0][2]), "+f"(Sacc[m][0][3])
                    : "r"(r0), "r"(r1), "r"(r2), "r"(r3), "r"(bx0), "r"(bx1));
                asm volatile(
                    "mma.sync.aligned.m16n8k16.row.col.f32.f16.f16.f32 "
                    "{%0,%1,%2,%3}, {%4,%5,%6,%7}, {%8,%9}, {%0,%1,%2,%3};"
                    : "+f"(Sacc[m][1][0]), "+f"(Sacc[m][1][1]), "+f"(Sacc[m][1][2]), "+f"(Sacc[m][1][3])
                    : "r"(r0), "r"(r1), "r"(r2), "r"(r3), "r"(bx2), "r"(bx3));
            }
        }

        // store S row (fragment-native layout, coalesced 8B stores)
        __half2* Sp2 = (__half2*)(Sbuf + (size_t)dl * SROW);
        #pragma unroll
        for (int m = 0; m < 4; ++m)
            #pragma unroll
            for (int rh = 0; rh < 2; ++rh) {
                int u0 = (((w * 4 + m) * 2 + rh) * 8 + gg) * 8 + t4 * 2;
                __half2 p0 = __floats2half2_rn(Sacc[m][0][rh * 2], Sacc[m][0][rh * 2 + 1]);
                __half2 p1 = __floats2half2_rn(Sacc[m][1][rh * 2], Sacc[m][1][rh * 2 + 1]);
                uint2 pv;
                pv.x = *(unsigned*)&p0;
                pv.y = *(unsigned*)&p1;
                *(uint2*)&Sp2[u0] = pv;
            }
        if (t < 16) g_Xsum[(d0 + dl) * 16 + t] = xsum;
        dl = dl2;
    }
}

// --- role B: K2 MMA over a j-slice for chunk cc ---
__device__ __forceinline__ void k2_role(unsigned char* sm, int bid, int cc, int dn)
{
    __half* As = (__half*)sm;
    __half* Bs = (__half*)(sm + 128 * AS_STRIDE * 2);
    const __half* Sbuf = g_Sh[cc & 1];
    float* Pbuf = g_P[cc & 1];

    int tid  = threadIdx.x;
    int warp = tid >> 5;
    int lane = tid & 31;
    int g    = lane >> 2;
    int t4   = lane & 3;
    int slice = bid & (JSLICE - 1);
    int r0    = (bid >> 3) * 128;
    int jbase = slice * JLEN;

    float c0[4], c1[4], c2[4], c3[4];
    #pragma unroll
    for (int nt = 0; nt < 4; ++nt) { c0[nt] = 0.f; c1[nt] = 0.f; c2[nt] = 0.f; c3[nt] = 0.f; }

    for (int it = 0; it < JLEN / 64; ++it) {
        int j0 = jbase + it * 64;
        __syncthreads();
        #pragma unroll
        for (int u = 0; u < 4; ++u) {
            int idx = tid + u * 256;
            int row = idx >> 3;
            int q   = idx & 7;
            int rl  = r0 + row; if (rl >= dn) rl = dn - 1;
            *(uint4*)&As[row * AS_STRIDE + q * 8] =
                ((const uint4*)(Sbuf + (size_t)rl * SROW + j0))[q];
        }
        {
            int row = tid >> 3;
            int q   = tid & 7;
            *(uint4*)&Bs[row * AS_STRIDE + q * 8] =
                ((const uint4*)(g_w2t + (size_t)row * SROW + j0))[q];
        }
        __syncthreads();

        #pragma unroll
        for (int kk = 0; kk < 64; kk += 16) {
            unsigned a0 = *(const unsigned*)&As[(warp * 16 + g    ) * AS_STRIDE + kk     + 2 * t4];
            unsigned a1 = *(const unsigned*)&As[(warp * 16 + g + 8) * AS_STRIDE + kk     + 2 * t4];
            unsigned a2 = *(const unsigned*)&As[(warp * 16 + g    ) * AS_STRIDE + kk + 8 + 2 * t4];
            unsigned a3 = *(const unsigned*)&As[(warp * 16 + g + 8) * AS_STRIDE + kk + 8 + 2 * t4];
            #pragma unroll
            for (int nt = 0; nt < 4; ++nt) {
                unsigned b0 = *(const unsigned*)&Bs[(nt * 8 + g) * AS_STRIDE + kk     + 2 * t4];
                unsigned b1 = *(const unsigned*)&Bs[(nt * 8 + g) * AS_STRIDE + kk + 8 + 2 * t4];
                asm volatile(
                    "mma.sync.aligned.m16n8k16.row.col.f32.f16.f16.f32 "
                    "{%0,%1,%2,%3}, {%4,%5,%6,%7}, {%8,%9}, {%0,%1,%2,%3};"
                    : "+f"(c0[nt]), "+f"(c1[nt]), "+f"(c2[nt]), "+f"(c3[nt])
                    : "r"(a0), "r"(a1), "r"(a2), "r"(a3), "r"(b0), "r"(b1));
            }
        }
    }

    #pragma unroll
    for (int nt = 0; nt < 4; ++nt) {
        int row = r0 + warp * 16 + g;
        int col = nt * 8 + 2 * t4;
        if (row < dn)
            *(float2*)&Pbuf[((size_t)slice * CH + row) * 32 + col] = make_float2(c0[nt], c1[nt]);
        if (row + 8 < dn)
            *(float2*)&Pbuf[((size_t)slice * CH + row + 8) * 32 + col] = make_float2(c2[nt], c3[nt]);
    }
}

// --- role C: reduce partials + NNConv epilogue for chunk cc ---
__device__ __forceinline__ void red_role(
    int bid, int cc, int dn,
    const float* __restrict__ b2, const float* __restrict__ x,
    const float* __restrict__ root, const float* __restrict__ nn_bias)
{
    int gid = bid * 256 + threadIdx.x;
    if (gid >= dn * 32) return;
    const float* Pbuf = g_P[cc & 1];
    int rl = gid >> 5, o = gid & 31;
    int d = cc * CH + rl;
    float v = nn_bias[o];
    #pragma unroll
    for (int s = 0; s < JSLICE; ++s)
        v += Pbuf[((size_t)s * CH + rl) * 32 + o];
    #pragma unroll
    for (int i = 0; i < 16; ++i)
        v = fmaf(g_Xsum[d * 16 + i], b2[i * 32 + o], v);
    #pragma unroll
    for (int c = 0; c < 16; ++c)
        v = fmaf(x[(size_t)d * 16 + c], root[c * 32 + o], v);
    g_x1[d * 32 + o] = fmaxf(v, 0.f);
}

// --- combo: block ranges -> roles ---
__global__ __launch_bounds__(256) void k_combo(
    const float* __restrict__ x, const float* __restrict__ b1,
    const float* __restrict__ b2, const float* __restrict__ root,
    const float* __restrict__ nn_bias,
    int c, int nK2, int nK1, int dnK1, int dnK2, int dnRd)
{
    __shared__ __align__(16) unsigned char sm[(128 + 32) * AS_STRIDE * 2];
    int b = blockIdx.x;
    if (b < nK2) {
        k2_role(sm, b, c - 1, dnK2);
    } else if (b < nK2 + nK1) {
        k1_role(sm, b - nK2, nK1, c, dnK1, b1);
    } else {
        red_role(b - nK2 - nK1, c - 2, dnRd, b2, x, root, nn_bias);
    }
}

// ---------------- K3: xw = x1 @ gcn_w ----------------
__global__ void k3_xw(const float* __restrict__ gcn_w) {
    int gid = blockIdx.x * blockDim.x + threadIdx.x;
    if (gid >= NN * 32) return;
    int d = gid >> 5, o = gid & 31;
    float acc = 0.f;
    #pragma unroll
    for (int c = 0; c < 32; ++c)
        acc = fmaf(g_x1[d * 32 + c], gcn_w[c * 32 + o], acc);
    g_xw[gid] = acc;
}

// ---------------- K4: GCN aggregate via CSR (warp per dst) ----------------
__global__ void k4_gcn(const float* __restrict__ gcn_b) {
    int wid = (blockIdx.x * blockDim.x + threadIdx.x) >> 5;
    int lane = threadIdx.x & 31;
    int nwarps = (gridDim.x * blockDim.x) >> 5;
    for (int d = wid; d < NN; d += nwarps) {
        float dd = g_dis[d];
        float acc = 0.f;
        int beg = g_offs[d], end = g_offs[d + 1];
        for (int j = beg; j < end; ++j) {
            int e = g_elist[j];
            int s = g_src[e];
            acc = fmaf(g_dis[s], g_xw[s * 32 + lane], acc);
        }
        g_x2[d * 32 + lane] = gcn_b[lane] + dd * (dd * g_xw[d * 32 + lane] + acc);
    }
}

// ---------------- K5: edge scorer ----------------
__global__ void k5_score(const float* __restrict__ lin_w, const float* __restrict__ lin_b,
                         float* __restrict__ out) {
    int e = blockIdx.x * blockDim.x + threadIdx.x;
    if (e >= EE) return;
    int s = g_src[e], d = g_dst[e];
    const float4* a = (const float4*)(g_x2 + (size_t)s * 32);
    const float4* b = (const float4*)(g_x2 + (size_t)d * 32);
    const float4* w = (const float4*)lin_w;
    float acc = lin_b[0];
    #pragma unroll
    for (int q = 0; q < 8; ++q) {
        float4 av = a[q], wv = w[q];
        acc += av.x * wv.x + av.y * wv.y + av.z * wv.z + av.w * wv.w;
    }
    #pragma unroll
    for (int q = 0; q < 8; ++q) {
        float4 bv = b[q], wv = w[8 + q];
        acc += bv.x * wv.x + bv.y * wv.y + bv.z * wv.z + bv.w * wv.w;
    }
    out[e] = 1.f / (1.f + expf(-acc));
}

// ---------------- launch ----------------
static inline int dn_of(int c) {
    if (c < 0 || c >= NCHUNK) return 0;
    int d0 = c * CH;
    int dn = NN - d0;
    if (dn > CH) dn = CH;
    return dn > 0 ? dn : 0;
}

extern "C" void kernel_launch(void* const* d_in, const int* in_sizes, int n_in,
                              void* d_out, int out_size) {
    const float* x       = (const float*)d_in[0];
    const void*  ei      = d_in[1];
    const float* ea      = (const float*)d_in[2];
    const float* w1      = (const float*)d_in[3];
    const float* b1      = (const float*)d_in[4];
    const float* w2      = (const float*)d_in[5];
    const float* b2      = (const float*)d_in[6];
    const float* root    = (const float*)d_in[7];
    const float* nn_bias = (const float*)d_in[8];
    const float* gcn_w   = (const float*)d_in[9];
    const float* gcn_b   = (const float*)d_in[10];
    const float* lin_w   = (const float*)d_in[11];
    const float* lin_b   = (const float*)d_in[12];
    float*       out     = (float*)d_out;

    k_dzw<<<(32 * SROW + 255) / 256, 256>>>(ei, w2, w1);
    k_prep<<<(EE + 255) / 256, 256>>>(ei);
    k_scan<<<1, 1024>>>();
    k_scatter<<<(EE + 255) / 256, 256>>>();
    k_pack<<<(EE * 32 + 255) / 256, 256>>>(x, ea);

    // software pipeline: combo(c) = k2(c-1) || k1(c) || reduce(c-2)
    for (int c = 0; c <= NCHUNK + 1; ++c) {
        int dnK1 = dn_of(c);
        int dnK2 = dn_of(c - 1);
        int dnRd = dn_of(c - 2);
        int nK2 = dnK2 ? ((dnK2 + 127) / 128) * JSLICE : 0;
        int nK1 = dnK1 ? (dnK1 < K1GRID ? dnK1 : K1GRID) : 0;
        int nRd = dnRd ? (dnRd * 32 + 255) / 256 : 0;
        int grid = nK2 + nK1 + nRd;
        if (grid > 0)
            k_combo<<<grid, 256>>>(x, b1, b2, root, nn_bias, c, nK2, nK1, dnK1, dnK2, dnRd);
    }

    k3_xw<<<(NN * 32 + 255) / 256, 256>>>(gcn_w);
    k4_gcn<<<512, 256>>>(gcn_b);
    k5_score<<<(EE + 255) / 256, 256>>>(lin_w, lin_b, out);
}